// round 12
// baseline (speedup 1.0000x reference)
#include <cuda_runtime.h>
#include <cstdint>

// ---------------- scratch (no allocation allowed) ----------------
__device__ float g_qkv[8192 * 3072];   // [B*S, 3*EMB], tf32-rounded by gemm epilogue
__device__ float g_att[8192 * 1024];   // [B*S, EMB], tf32-rounded by attn epilogue
__device__ float g_xr[8192 * 1024];    // x tf32-rounded
__device__ float g_wqT[3072 * 1024];   // W_qkv^T [N,K], tf32-rounded
__device__ float g_wpT[1024 * 1024];   // W_proj^T [N,K], tf32-rounded

// ---------------- helpers --------------------------------------
__device__ __forceinline__ uint32_t f2tf32(float v) {
    uint32_t u;
    asm("cvt.rna.tf32.f32 %0, %1;" : "=r"(u) : "f"(v));
    return u;
}
__device__ __forceinline__ float tf32f(float v) {
    return __uint_as_float(f2tf32(v));
}
__device__ __forceinline__ uint32_t cvta_smem(const void* p) {
    uint32_t a;
    asm("{ .reg .u64 t; cvta.to.shared.u64 t, %1; cvt.u32.u64 %0, t; }"
        : "=r"(a) : "l"(p));
    return a;
}
__device__ __forceinline__ void cp16(uint32_t dst, const void* src) {
    asm volatile("cp.async.cg.shared.global [%0], [%1], 16;"
                 :: "r"(dst), "l"(src) : "memory");
}
__device__ __forceinline__ uint4 ldsm_x4(uint32_t addr) {
    uint4 r;
    asm volatile("ldmatrix.sync.aligned.m8n8.x4.shared.b16 {%0,%1,%2,%3}, [%4];"
                 : "=r"(r.x), "=r"(r.y), "=r"(r.z), "=r"(r.w) : "r"(addr));
    return r;
}
__device__ __forceinline__ uint2 ldsm_x2(uint32_t addr) {
    uint2 r;
    asm volatile("ldmatrix.sync.aligned.m8n8.x2.shared.b16 {%0,%1}, [%2];"
                 : "=r"(r.x), "=r"(r.y) : "r"(addr));
    return r;
}
__device__ __forceinline__ void mma_tf32(float c[4], const uint4& a, const uint2& b) {
    asm volatile(
        "mma.sync.aligned.m16n8k8.row.col.f32.tf32.tf32.f32 "
        "{%0,%1,%2,%3}, {%4,%5,%6,%7}, {%8,%9}, {%0,%1,%2,%3};"
        : "+f"(c[0]), "+f"(c[1]), "+f"(c[2]), "+f"(c[3])
        : "r"(a.x), "r"(a.y), "r"(a.z), "r"(a.w), "r"(b.x), "r"(b.y));
}
// exp2 on MUFU pipe
__device__ __forceinline__ float exp2m(float x) {
    float r;
    asm("ex2.approx.ftz.f32 %0, %1;" : "=f"(r) : "f"(x));
    return r;
}

// ---------------- rna-round a float buffer (for x) -------------------------
__global__ __launch_bounds__(256) void round_rna_vec(
    const float4* __restrict__ in, float4* __restrict__ out, int n4)
{
    int i = blockIdx.x * blockDim.x + threadIdx.x;
    if (i < n4) {
        float4 v = in[i];
        v.x = tf32f(v.x); v.y = tf32f(v.y);
        v.z = tf32f(v.z); v.w = tf32f(v.w);
        out[i] = v;
    }
}

// ---------------- weight transpose + tf32 rounding ------------------------
__global__ __launch_bounds__(256) void transpose_rna(
    const float* __restrict__ in, float* __restrict__ out, int R, int C)
{
    __shared__ float t[32][33];
    const int c0 = blockIdx.x * 32, r0 = blockIdx.y * 32;
    const int x = threadIdx.x & 31, y = threadIdx.x >> 5;  // 32x8
    #pragma unroll
    for (int i = 0; i < 32; i += 8) {
        float v = in[(size_t)(r0 + y + i) * C + c0 + x];
        t[y + i][x] = tf32f(v);
    }
    __syncthreads();
    #pragma unroll
    for (int i = 0; i < 32; i += 8)
        out[(size_t)(c0 + y + i) * R + r0 + x] = t[x][y + i];
}

// ---------------- cp.async-pipelined tf32 GEMM + ldmatrix ------------------
// C[M,N] = A[M,K] @ BT[N,K]^T (+bias). Inputs tf32-pre-rounded.
// 128x128 CTA tile, BK=16, 256 thr = 4x2 warps. 5-stage cp.async pipeline,
// wait_group 3 = wait exactly for the group being consumed (R9 over-waited
// by one group with 4 stages / wait_group 2).
static constexpr int GP = 20;                       // smem row pitch (floats)
static constexpr int GSTAGE_FLOATS = 2 * 128 * GP;  // 5120 floats / stage
static constexpr int GEMM_SMEM = 5 * GSTAGE_FLOATS * 4;  // 102400 bytes

__global__ __launch_bounds__(256, 2) void gemm_cp(
    const float* __restrict__ A, const float* __restrict__ BT,
    const float* __restrict__ bias, float* __restrict__ C,
    int M, int N, int K, int round_out)
{
    extern __shared__ float gsm[];
    const uint32_t sbase = cvta_smem(gsm);

    const int tid  = threadIdx.x;
    const int wid  = tid >> 5, lane = tid & 31;
    const int wr   = wid & 3;            // warp row (m-tiles 2wr, 2wr+1)
    const int wc   = wid >> 2;           // warp col (n-tiles wc*8..+7)
    const int g    = lane >> 2, q = lane & 3;
    const int brow = blockIdx.y * 128, bcol = blockIdx.x * 128;

    // cp.async roles: thread -> tile row cr, 32B half cc
    const int cr = tid >> 1;
    const int cc = (tid & 1) * 32;
    const char* Asrc = (const char*)(A  + (size_t)(brow + cr) * K) + cc;
    const char* Bsrc = (const char*)(BT + (size_t)(bcol + cr) * K) + cc;

    const int iters = K >> 4;

    auto issue = [&](int it) {
        if (it < iters) {
            const uint32_t st = (uint32_t)(it % 5) * (GSTAGE_FLOATS * 4);
            const uint32_t da = sbase + st + cr * (GP * 4) + cc;
            const uint32_t db = da + 128 * GP * 4;
            const char* sa = Asrc + (size_t)it * 64;
            const char* sb = Bsrc + (size_t)it * 64;
            cp16(da,      sa);
            cp16(da + 16, sa + 16);
            cp16(db,      sb);
            cp16(db + 16, sb + 16);
        }
        asm volatile("cp.async.commit_group;" ::: "memory");
    };

    float acc[2][8][4];
    #pragma unroll
    for (int i = 0; i < 2; i++)
        #pragma unroll
        for (int j = 0; j < 8; j++)
            #pragma unroll
            for (int e = 0; e < 4; e++) acc[i][j][e] = 0.0f;

    // per-lane ldmatrix row offsets (bytes)
    const uint32_t aRowOff = (uint32_t)(lane & 15) * (GP * 4) + (lane >> 4) * 16;
    const uint32_t bRowOff = (uint32_t)(lane & 7) * (GP * 4) + ((lane >> 3) & 1) * 16;

    issue(0); issue(1); issue(2); issue(3);

    for (int it = 0; it < iters; it++) {
        asm volatile("cp.async.wait_group 3;" ::: "memory");
        __syncthreads();
        issue(it + 4);   // writes buf (it-1)%5, reads of which ended pre-sync

        const uint32_t stA = sbase + (uint32_t)(it % 5) * (GSTAGE_FLOATS * 4);
        const uint32_t stB = stA + 128 * GP * 4;

        #pragma unroll
        for (int s = 0; s < 2; s++) {
            uint4 af[2];
            #pragma unroll
            for (int i = 0; i < 2; i++)
                af[i] = ldsm_x4(stA + (uint32_t)((wr * 2 + i) * 16) * (GP * 4)
                                    + s * 32 + aRowOff);
            uint2 bf[8];
            #pragma unroll
            for (int j = 0; j < 8; j++)
                bf[j] = ldsm_x2(stB + (uint32_t)(wc * 64 + j * 8) * (GP * 4)
                                    + s * 32 + bRowOff);
            #pragma unroll
            for (int i = 0; i < 2; i++)
                #pragma unroll
                for (int j = 0; j < 8; j++)
                    mma_tf32(acc[i][j], af[i], bf[j]);
        }
    }

    #pragma unroll
    for (int i = 0; i < 2; i++) {
        const int row0 = brow + (wr * 2 + i) * 16 + g;
        #pragma unroll
        for (int j = 0; j < 8; j++) {
            const int col = bcol + wc * 64 + j * 8 + q * 2;
            float b0 = 0.0f, b1 = 0.0f;
            if (bias) { b0 = bias[col]; b1 = bias[col + 1]; }
            float2 v0, v1;
            v0.x = acc[i][j][0] + b0; v0.y = acc[i][j][1] + b1;
            v1.x = acc[i][j][2] + b0; v1.y = acc[i][j][3] + b1;
            if (round_out) {
                v0.x = tf32f(v0.x); v0.y = tf32f(v0.y);
                v1.x = tf32f(v1.x); v1.y = tf32f(v1.y);
            }
            *(float2*)&C[(size_t)row0 * N + col]       = v0;
            *(float2*)&C[(size_t)(row0 + 8) * N + col] = v1;
        }
    }
}

// ---------------- tf32 mma flash attention, BQ=128, BK=64 -----------------
// 256 threads = 8 warps; warp w owns q rows [w*16, w*16+16).
// Inputs tf32-pre-rounded -> raw cp.async staging. Q staged once; K/V
// double-buffered cp.async. Q/K frags via ldmatrix; V scalar conflict-free;
// P reused in registers via sigma(kv) permutation. Softmax: single FMA folds
// 1/8*log2e + max-subtract; all exp on MUFU (2 ops/value).
static constexpr int AP = 68;                 // pitch floats (272B rows)
static constexpr int QF = 128 * AP;           // Q floats
static constexpr int KVF = 64 * AP;           // K or V tile floats
static constexpr int ATTN_SMEM = (QF + 4 * KVF) * 4;  // 104448 bytes

__global__ __launch_bounds__(256, 2) void attn_tc(
    const float* __restrict__ qkv, float* __restrict__ out)
{
    extern __shared__ float sm[];
    const uint32_t sbase = cvta_smem(sm);

    const int qt = (int)gridDim.x - 1 - (int)blockIdx.x;  // heavy tiles first
    const int h  = blockIdx.y;
    const int b  = blockIdx.z;
    const int tid = threadIdx.x, w = tid >> 5, lane = tid & 31;
    const int g = lane >> 2, q = lane & 3;
    const int S = 2048, D3 = 3072;
    const float C = 0.1803368801f;            // 0.125 * log2(e)

    const uint32_t qBase  = sbase;
    const uint32_t kBase0 = sbase + QF * 4;
    const uint32_t vBase0 = sbase + (QF + 2 * KVF) * 4;

    const float* Qb = qkv + ((size_t)(b * S) + qt * 128) * D3 + h * 64;
    const float* KVb = qkv + (size_t)(b * S) * D3 + 1024 + h * 64;

    // ---- stage Q raw ----
    {
        const int ch0 = tid * 8;
        #pragma unroll
        for (int i = 0; i < 8; i++) {
            const int ch = ch0 + i;
            const int r = ch >> 4, c16 = ch & 15;
            cp16(qBase + (uint32_t)r * (AP * 4) + c16 * 16,
                 Qb + (size_t)r * D3 + c16 * 4);
        }
    }

    const int ktmax = 2 * qt + 1;
    const int kvr = tid >> 2;
    const int kvc = (tid & 3) * 16;
    auto issueKV = [&](int kt, int buf) {
        if (kt <= ktmax) {
            const float* Kb = KVb + (size_t)(kt * 64 + kvr) * D3 + kvc;
            const uint32_t kd = kBase0 + (uint32_t)buf * (KVF * 4)
                              + (uint32_t)kvr * (AP * 4) + kvc * 4;
            const uint32_t vd = vBase0 + (uint32_t)buf * (KVF * 4)
                              + (uint32_t)kvr * (AP * 4) + kvc * 4;
            #pragma unroll
            for (int c = 0; c < 4; c++) {
                cp16(kd + c * 16, Kb + c * 4);
                cp16(vd + c * 16, Kb + 1024 + c * 4);
            }
        }
        asm volatile("cp.async.commit_group;" ::: "memory");
    };

    issueKV(0, 0);

    float s[8][4], o[8][4];
    float m0 = -1e30f, m1 = -1e30f, l0 = 0.0f, l1 = 0.0f;
    #pragma unroll
    for (int j = 0; j < 8; j++)
        #pragma unroll
        for (int e = 0; e < 4; e++) o[j][e] = 0.0f;

    const int pr = w * 16 + g;
    const uint32_t bRowOff = (uint32_t)(lane & 7) * (AP * 4) + ((lane >> 3) & 1) * 16;
    const uint32_t aRowOff = (uint32_t)(lane & 15) * (AP * 4) + (lane >> 4) * 16;
    const uint32_t qWarp = qBase + (uint32_t)(w * 16) * (AP * 4) + aRowOff;

    for (int kt = 0; kt <= ktmax; kt++) {
        issueKV(kt + 1, (kt + 1) & 1);
        asm volatile("cp.async.wait_group 1;" ::: "memory");
        __syncthreads();

        const int buf = kt & 1;
        const uint32_t kB = kBase0 + (uint32_t)buf * (KVF * 4);
        const float* Vs = sm + QF + 2 * KVF + buf * KVF;

        // ---- S = Q @ K^T (raw scores; 1/8 folded into exp arg) ----
        #pragma unroll
        for (int j = 0; j < 8; j++)
            #pragma unroll
            for (int e = 0; e < 4; e++) s[j][e] = 0.0f;

        #pragma unroll
        for (int kc = 0; kc < 8; kc++) {
            const uint4 a = ldsm_x4(qWarp + kc * 32);
            #pragma unroll
            for (int nt = 0; nt < 8; nt++) {
                const uint2 bb = ldsm_x2(kB + (uint32_t)(nt * 8) * (AP * 4)
                                            + kc * 32 + bRowOff);
                mma_tf32(s[nt], a, bb);
            }
        }

        // ---- causal mask on diagonal tiles (raw domain) ----
        if (kt >= 2 * qt) {
            const int r0  = qt * 128 + pr;
            const int kvb = kt * 64 + 2 * q;
            #pragma unroll
            for (int nt = 0; nt < 8; nt++) {
                const int c = kvb + nt * 8;
                if (c     > r0)     s[nt][0] = -1e30f;
                if (c + 1 > r0)     s[nt][1] = -1e30f;
                if (c     > r0 + 8) s[nt][2] = -1e30f;
                if (c + 1 > r0 + 8) s[nt][3] = -1e30f;
            }
        }

        // ---- online softmax: max over raw s ----
        float mx0 = -1e30f, mx1 = -1e30f;
        #pragma unroll
        for (int nt = 0; nt < 8; nt++) {
            mx0 = fmaxf(mx0, fmaxf(s[nt][0], s[nt][1]));
            mx1 = fmaxf(mx1, fmaxf(s[nt][2], s[nt][3]));
        }
        mx0 = fmaxf(mx0, __shfl_xor_sync(0xffffffffu, mx0, 1, 4));
        mx0 = fmaxf(mx0, __shfl_xor_sync(0xffffffffu, mx0, 2, 4));
        mx1 = fmaxf(mx1, __shfl_xor_sync(0xffffffffu, mx1, 1, 4));
        mx1 = fmaxf(mx1, __shfl_xor_sync(0xffffffffu, mx1, 2, 4));

        const float mn0 = fmaxf(m0, mx0), mn1 = fmaxf(m1, mx1);
        const float mnC0 = mn0 * C, mnC1 = mn1 * C;
        const float al0 = exp2m(fmaf(m0, C, -mnC0));
        const float al1 = exp2m(fmaf(m1, C, -mnC1));
        m0 = mn0; m1 = mn1;

        // ---- exp2 (MUFU), one FMA per value ----
        float rs0 = 0.0f, rs1 = 0.0f;
        #pragma unroll
        for (int nt = 0; nt < 8; nt++) {
            s[nt][0] = exp2m(fmaf(s[nt][0], C, -mnC0));
            s[nt][1] = exp2m(fmaf(s[nt][1], C, -mnC0));
            s[nt][2] = exp2m(fmaf(s[nt][2], C, -mnC1));
            s[nt][3] = exp2m(fmaf(s[nt][3], C, -mnC1));
            rs0 += s[nt][0] + s[nt][1];
            rs1 += s[nt][2] + s[nt][3];
        }
        rs0 += __shfl_xor_sync(0xffffffffu, rs0, 1, 4);
        rs0 += __shfl_xor_sync(0xffffffffu, rs0, 2, 4);
        rs1 += __shfl_xor_sync(0xffffffffu, rs1, 1, 4);
        rs1 += __shfl_xor_sync(0xffffffffu, rs1, 2, 4);
        l0 = l0 * al0 + rs0;
        l1 = l1 * al1 + rs1;

        #pragma unroll
        for (int j = 0; j < 8; j++) {
            o[j][0] *= al0; o[j][1] *= al0;
            o[j][2] *= al1; o[j][3] *= al1;
        }

        // ---- O += P @ V (P C-frag as A-frag via sigma permutation) ----
        #pragma unroll
        for (int kc = 0; kc < 8; kc++) {
            uint4 a;
            a.x = f2tf32(s[kc][0]);
            a.y = f2tf32(s[kc][2]);
            a.z = f2tf32(s[kc][1]);
            a.w = f2tf32(s[kc][3]);
            const float* vr = &Vs[(kc * 8 + 2 * q) * AP];
            #pragma unroll
            for (int nd = 0; nd < 8; nd++) {
                uint2 bb;
                bb.x = __float_as_uint(vr[nd * 8 + g]);
                bb.y = __float_as_uint(vr[AP + nd * 8 + g]);
                mma_tf32(o[nd], a, bb);
            }
        }
        __syncthreads();   // all reads of buf kt&1 done before reuse at kt+2
    }

    // ---- epilogue: normalize, tf32-round (feeds proj GEMM), store ----
    float* ob = out + ((size_t)(b * S) + qt * 128) * 1024 + h * 64;
    const float inv0 = 1.0f / l0, inv1 = 1.0f / l1;
    #pragma unroll
    for (int nd = 0; nd < 8; nd++) {
        const int c = nd * 8 + 2 * q;
        float2 v0, v1;
        v0.x = tf32f(o[nd][0] * inv0); v0.y = tf32f(o[nd][1] * inv0);
        v1.x = tf32f(o[nd][2] * inv1); v1.y = tf32f(o[nd][3] * inv1);
        *(float2*)&ob[(size_t)pr * 1024 + c]       = v0;
        *(float2*)&ob[(size_t)(pr + 8) * 1024 + c] = v1;
    }
}

// ---------------- launch -------------------------------------------------
extern "C" void kernel_launch(void* const* d_in, const int* in_sizes, int n_in,
                              void* d_out, int out_size)
{
    const float* x      = (const float*)d_in[0];   // [4,2048,1024]
    const float* W_qkv  = (const float*)d_in[1];   // [1024,3072]
    const float* W_proj = (const float*)d_in[2];   // [1024,1024]
    const float* b_proj = (const float*)d_in[3];   // [1024]
    float* out = (float*)d_out;

    float *qkv = nullptr, *att = nullptr, *xr = nullptr, *wqT = nullptr, *wpT = nullptr;
    cudaGetSymbolAddress((void**)&qkv, g_qkv);
    cudaGetSymbolAddress((void**)&att, g_att);
    cudaGetSymbolAddress((void**)&xr,  g_xr);
    cudaGetSymbolAddress((void**)&wqT, g_wqT);
    cudaGetSymbolAddress((void**)&wpT, g_wpT);

    cudaFuncSetAttribute(attn_tc,
                         cudaFuncAttributeMaxDynamicSharedMemorySize, ATTN_SMEM);
    cudaFuncSetAttribute(gemm_cp,
                         cudaFuncAttributeMaxDynamicSharedMemorySize, GEMM_SMEM);

    const int M = 8192;

    // 0) pre-round x; transpose+round weights
    round_rna_vec<<<(M * 1024 / 4 + 255) / 256, 256>>>(
        (const float4*)x, (float4*)xr, M * 1024 / 4);
    transpose_rna<<<dim3(3072 / 32, 1024 / 32), 256>>>(W_qkv, wqT, 1024, 3072);
    transpose_rna<<<dim3(1024 / 32, 1024 / 32), 256>>>(W_proj, wpT, 1024, 1024);

    // 1) qkv = x @ W_qkv  (rounded output for raw attn staging)
    gemm_cp<<<dim3(3072 / 128, M / 128), 256, GEMM_SMEM>>>(
        xr, wqT, nullptr, qkv, M, 3072, 1024, 1);

    // 2) causal flash attention (tf32 mma.sync, cp.async pipelined)
    attn_tc<<<dim3(16, 16, 4), 256, ATTN_SMEM>>>(qkv, att);

    // 3) out = att @ W_proj + b_proj  (final output, unrounded)
    gemm_cp<<<dim3(1024 / 128, M / 128), 256, GEMM_SMEM>>>(
        att, wpT, b_proj, out, M, 1024, 1024, 0);
}

// round 13
// speedup vs baseline: 1.0195x; 1.0195x over previous
#include <cuda_runtime.h>
#include <cstdint>

// ---------------- scratch (no allocation allowed) ----------------
__device__ float g_qkv[8192 * 3072];   // [B*S, 3*EMB], tf32-rounded by gemm epilogue
__device__ float g_att[8192 * 1024];   // [B*S, EMB], tf32-rounded by attn epilogue
__device__ float g_xr[8192 * 1024];    // x tf32-rounded
__device__ float g_wqT[3072 * 1024];   // W_qkv^T [N,K], tf32-rounded
__device__ float g_wpT[1024 * 1024];   // W_proj^T [N,K], tf32-rounded

// ---------------- helpers --------------------------------------
__device__ __forceinline__ uint32_t f2tf32(float v) {
    uint32_t u;
    asm("cvt.rna.tf32.f32 %0, %1;" : "=r"(u) : "f"(v));
    return u;
}
__device__ __forceinline__ float tf32f(float v) {
    return __uint_as_float(f2tf32(v));
}
__device__ __forceinline__ uint32_t cvta_smem(const void* p) {
    uint32_t a;
    asm("{ .reg .u64 t; cvta.to.shared.u64 t, %1; cvt.u32.u64 %0, t; }"
        : "=r"(a) : "l"(p));
    return a;
}
__device__ __forceinline__ void cp16(uint32_t dst, const void* src) {
    asm volatile("cp.async.cg.shared.global [%0], [%1], 16;"
                 :: "r"(dst), "l"(src) : "memory");
}
__device__ __forceinline__ uint4 ldsm_x4(uint32_t addr) {
    uint4 r;
    asm volatile("ldmatrix.sync.aligned.m8n8.x4.shared.b16 {%0,%1,%2,%3}, [%4];"
                 : "=r"(r.x), "=r"(r.y), "=r"(r.z), "=r"(r.w) : "r"(addr));
    return r;
}
__device__ __forceinline__ void mma_tf32(float c[4], const uint4& a, const uint2& b) {
    asm volatile(
        "mma.sync.aligned.m16n8k8.row.col.f32.tf32.tf32.f32 "
        "{%0,%1,%2,%3}, {%4,%5,%6,%7}, {%8,%9}, {%0,%1,%2,%3};"
        : "+f"(c[0]), "+f"(c[1]), "+f"(c[2]), "+f"(c[3])
        : "r"(a.x), "r"(a.y), "r"(a.z), "r"(a.w), "r"(b.x), "r"(b.y));
}
// exp2 on MUFU pipe
__device__ __forceinline__ float exp2m(float x) {
    float r;
    asm("ex2.approx.ftz.f32 %0, %1;" : "=f"(r) : "f"(x));
    return r;
}

// ---------------- rna-round a float buffer (for x) -------------------------
__global__ __launch_bounds__(256) void round_rna_vec(
    const float4* __restrict__ in, float4* __restrict__ out, int n4)
{
    int i = blockIdx.x * blockDim.x + threadIdx.x;
    if (i < n4) {
        float4 v = in[i];
        v.x = tf32f(v.x); v.y = tf32f(v.y);
        v.z = tf32f(v.z); v.w = tf32f(v.w);
        out[i] = v;
    }
}

// ---------------- weight transpose + tf32 rounding ------------------------
__global__ __launch_bounds__(256) void transpose_rna(
    const float* __restrict__ in, float* __restrict__ out, int R, int C)
{
    __shared__ float t[32][33];
    const int c0 = blockIdx.x * 32, r0 = blockIdx.y * 32;
    const int x = threadIdx.x & 31, y = threadIdx.x >> 5;  // 32x8
    #pragma unroll
    for (int i = 0; i < 32; i += 8) {
        float v = in[(size_t)(r0 + y + i) * C + c0 + x];
        t[y + i][x] = tf32f(v);
    }
    __syncthreads();
    #pragma unroll
    for (int i = 0; i < 32; i += 8)
        out[(size_t)(c0 + y + i) * R + r0 + x] = t[x][y + i];
}

// ---------------- cp.async-pipelined tf32 GEMM + ldmatrix ------------------
// C[M,N] = A[M,K] @ BT[N,K]^T (+bias). Inputs tf32-pre-rounded.
// 128x128 CTA tile, BK=16, 256 thr = 4x2 warps, 4-stage cp.async pipeline
// (R9 config). B-fragments via ldsm_x4 spanning BOTH k-steps (matrices at
// byte-cols 0/16/32/48 of the same 8 rows): 12 LDSM / warp-iter (was 20).
static constexpr int GP = 20;                       // smem row pitch (floats)
static constexpr int GSTAGE_FLOATS = 2 * 128 * GP;  // 5120 floats / stage
static constexpr int GEMM_SMEM = 4 * GSTAGE_FLOATS * 4;  // 81920 bytes

__global__ __launch_bounds__(256, 2) void gemm_cp(
    const float* __restrict__ A, const float* __restrict__ BT,
    const float* __restrict__ bias, float* __restrict__ C,
    int M, int N, int K, int round_out)
{
    extern __shared__ float gsm[];
    const uint32_t sbase = cvta_smem(gsm);

    const int tid  = threadIdx.x;
    const int wid  = tid >> 5, lane = tid & 31;
    const int wr   = wid & 3;            // warp row (m-tiles 2wr, 2wr+1)
    const int wc   = wid >> 2;           // warp col (n-tiles wc*8..+7)
    const int g    = lane >> 2, q = lane & 3;
    const int brow = blockIdx.y * 128, bcol = blockIdx.x * 128;

    // cp.async roles: thread -> tile row cr, 32B half cc
    const int cr = tid >> 1;
    const int cc = (tid & 1) * 32;
    const char* Asrc = (const char*)(A  + (size_t)(brow + cr) * K) + cc;
    const char* Bsrc = (const char*)(BT + (size_t)(bcol + cr) * K) + cc;

    const int iters = K >> 4;

    auto issue = [&](int it) {
        if (it < iters) {
            const uint32_t st = (uint32_t)(it & 3) * (GSTAGE_FLOATS * 4);
            const uint32_t da = sbase + st + cr * (GP * 4) + cc;
            const uint32_t db = da + 128 * GP * 4;
            const char* sa = Asrc + (size_t)it * 64;
            const char* sb = Bsrc + (size_t)it * 64;
            cp16(da,      sa);
            cp16(da + 16, sa + 16);
            cp16(db,      sb);
            cp16(db + 16, sb + 16);
        }
        asm volatile("cp.async.commit_group;" ::: "memory");
    };

    float acc[2][8][4];
    #pragma unroll
    for (int i = 0; i < 2; i++)
        #pragma unroll
        for (int j = 0; j < 8; j++)
            #pragma unroll
            for (int e = 0; e < 4; e++) acc[i][j][e] = 0.0f;

    // per-lane ldmatrix row offsets (bytes)
    const uint32_t aRowOff  = (uint32_t)(lane & 15) * (GP * 4) + (lane >> 4) * 16;
    const uint32_t b4RowOff = (uint32_t)(lane & 7) * (GP * 4) + (lane >> 3) * 16;

    issue(0); issue(1); issue(2);

    for (int it = 0; it < iters; it++) {
        asm volatile("cp.async.wait_group 2;" ::: "memory");
        __syncthreads();
        issue(it + 3);

        const uint32_t stA = sbase + (uint32_t)(it & 3) * (GSTAGE_FLOATS * 4);
        const uint32_t stB = stA + 128 * GP * 4;

        // A frags for both ksteps (4 ldsm_x4)
        uint4 af[2][2];
        #pragma unroll
        for (int s = 0; s < 2; s++)
            #pragma unroll
            for (int i = 0; i < 2; i++)
                af[s][i] = ldsm_x4(stA + (uint32_t)((wr * 2 + i) * 16) * (GP * 4)
                                       + s * 32 + aRowOff);

        // B frags: one ldsm_x4 per n-tile covers both ksteps
        #pragma unroll
        for (int jq = 0; jq < 2; jq++) {
            uint4 b4[4];
            #pragma unroll
            for (int j = 0; j < 4; j++)
                b4[j] = ldsm_x4(stB
                    + (uint32_t)((wc * 64 + (jq * 4 + j) * 8)) * (GP * 4)
                    + b4RowOff);
            #pragma unroll
            for (int j = 0; j < 4; j++) {
                const uint2 b0 = make_uint2(b4[j].x, b4[j].y);  // kstep 0
                const uint2 b1 = make_uint2(b4[j].z, b4[j].w);  // kstep 1
                #pragma unroll
                for (int i = 0; i < 2; i++) {
                    mma_tf32(acc[i][jq * 4 + j], af[0][i], b0);
                    mma_tf32(acc[i][jq * 4 + j], af[1][i], b1);
                }
            }
        }
    }

    #pragma unroll
    for (int i = 0; i < 2; i++) {
        const int row0 = brow + (wr * 2 + i) * 16 + g;
        #pragma unroll
        for (int j = 0; j < 8; j++) {
            const int col = bcol + wc * 64 + j * 8 + q * 2;
            float b0 = 0.0f, b1 = 0.0f;
            if (bias) { b0 = bias[col]; b1 = bias[col + 1]; }
            float2 v0, v1;
            v0.x = acc[i][j][0] + b0; v0.y = acc[i][j][1] + b1;
            v1.x = acc[i][j][2] + b0; v1.y = acc[i][j][3] + b1;
            if (round_out) {
                v0.x = tf32f(v0.x); v0.y = tf32f(v0.y);
                v1.x = tf32f(v1.x); v1.y = tf32f(v1.y);
            }
            *(float2*)&C[(size_t)row0 * N + col]       = v0;
            *(float2*)&C[(size_t)(row0 + 8) * N + col] = v1;
        }
    }
}

// ---------------- tf32 mma flash attention, BQ=128, BK=64 -----------------
// 256 threads = 8 warps; warp w owns q rows [w*16, w*16+16).
// Inputs tf32-pre-rounded -> raw cp.async staging. Q staged once; K/V
// double-buffered cp.async. Q frags via ldsm_x4; K frags via ldsm_x4
// spanning TWO ksteps each (32 LDSM, was 64); V scalar conflict-free;
// P reused in registers via sigma(kv) permutation. Softmax: single FMA
// folds 1/8*log2e + max-subtract; exp on MUFU.
static constexpr int AP = 68;                 // pitch floats (272B rows)
static constexpr int QF = 128 * AP;           // Q floats
static constexpr int KVF = 64 * AP;           // K or V tile floats
static constexpr int ATTN_SMEM = (QF + 4 * KVF) * 4;  // 104448 bytes

__global__ __launch_bounds__(256, 2) void attn_tc(
    const float* __restrict__ qkv, float* __restrict__ out)
{
    extern __shared__ float sm[];
    const uint32_t sbase = cvta_smem(sm);

    const int qt = (int)gridDim.x - 1 - (int)blockIdx.x;  // heavy tiles first
    const int h  = blockIdx.y;
    const int b  = blockIdx.z;
    const int tid = threadIdx.x, w = tid >> 5, lane = tid & 31;
    const int g = lane >> 2, q = lane & 3;
    const int S = 2048, D3 = 3072;
    const float C = 0.1803368801f;            // 0.125 * log2(e)

    const uint32_t qBase  = sbase;
    const uint32_t kBase0 = sbase + QF * 4;
    const uint32_t vBase0 = sbase + (QF + 2 * KVF) * 4;

    const float* Qb = qkv + ((size_t)(b * S) + qt * 128) * D3 + h * 64;
    const float* KVb = qkv + (size_t)(b * S) * D3 + 1024 + h * 64;

    // ---- stage Q raw ----
    {
        const int ch0 = tid * 8;
        #pragma unroll
        for (int i = 0; i < 8; i++) {
            const int ch = ch0 + i;
            const int r = ch >> 4, c16 = ch & 15;
            cp16(qBase + (uint32_t)r * (AP * 4) + c16 * 16,
                 Qb + (size_t)r * D3 + c16 * 4);
        }
    }

    const int ktmax = 2 * qt + 1;
    const int kvr = tid >> 2;
    const int kvc = (tid & 3) * 16;
    auto issueKV = [&](int kt, int buf) {
        if (kt <= ktmax) {
            const float* Kb = KVb + (size_t)(kt * 64 + kvr) * D3 + kvc;
            const uint32_t kd = kBase0 + (uint32_t)buf * (KVF * 4)
                              + (uint32_t)kvr * (AP * 4) + kvc * 4;
            const uint32_t vd = vBase0 + (uint32_t)buf * (KVF * 4)
                              + (uint32_t)kvr * (AP * 4) + kvc * 4;
            #pragma unroll
            for (int c = 0; c < 4; c++) {
                cp16(kd + c * 16, Kb + c * 4);
                cp16(vd + c * 16, Kb + 1024 + c * 4);
            }
        }
        asm volatile("cp.async.commit_group;" ::: "memory");
    };

    issueKV(0, 0);

    float s[8][4], o[8][4];
    float m0 = -1e30f, m1 = -1e30f, l0 = 0.0f, l1 = 0.0f;
    #pragma unroll
    for (int j = 0; j < 8; j++)
        #pragma unroll
        for (int e = 0; e < 4; e++) o[j][e] = 0.0f;

    const int pr = w * 16 + g;
    const uint32_t aRowOff  = (uint32_t)(lane & 15) * (AP * 4) + (lane >> 4) * 16;
    const uint32_t b4RowOff = (uint32_t)(lane & 7) * (AP * 4) + (lane >> 3) * 16;
    const uint32_t qWarp = qBase + (uint32_t)(w * 16) * (AP * 4) + aRowOff;

    for (int kt = 0; kt <= ktmax; kt++) {
        issueKV(kt + 1, (kt + 1) & 1);
        asm volatile("cp.async.wait_group 1;" ::: "memory");
        __syncthreads();

        const int buf = kt & 1;
        const uint32_t kB = kBase0 + (uint32_t)buf * (KVF * 4);
        const float* Vs = sm + QF + 2 * KVF + buf * KVF;

        // ---- S = Q @ K^T : K frags via ldsm_x4 spanning 2 ksteps ----
        #pragma unroll
        for (int j = 0; j < 8; j++)
            #pragma unroll
            for (int e = 0; e < 4; e++) s[j][e] = 0.0f;

        #pragma unroll
        for (int kc2 = 0; kc2 < 4; kc2++) {
            const uint4 a0 = ldsm_x4(qWarp + (2 * kc2) * 32);
            const uint4 a1 = ldsm_x4(qWarp + (2 * kc2 + 1) * 32);
            #pragma unroll
            for (int nt = 0; nt < 8; nt++) {
                const uint4 k4 = ldsm_x4(kB + (uint32_t)(nt * 8) * (AP * 4)
                                            + kc2 * 64 + b4RowOff);
                mma_tf32(s[nt], a0, make_uint2(k4.x, k4.y));
                mma_tf32(s[nt], a1, make_uint2(k4.z, k4.w));
            }
        }

        // ---- causal mask on diagonal tiles (raw domain) ----
        if (kt >= 2 * qt) {
            const int r0  = qt * 128 + pr;
            const int kvb = kt * 64 + 2 * q;
            #pragma unroll
            for (int nt = 0; nt < 8; nt++) {
                const int c = kvb + nt * 8;
                if (c     > r0)     s[nt][0] = -1e30f;
                if (c + 1 > r0)     s[nt][1] = -1e30f;
                if (c     > r0 + 8) s[nt][2] = -1e30f;
                if (c + 1 > r0 + 8) s[nt][3] = -1e30f;
            }
        }

        // ---- online softmax: max over raw s ----
        float mx0 = -1e30f, mx1 = -1e30f;
        #pragma unroll
        for (int nt = 0; nt < 8; nt++) {
            mx0 = fmaxf(mx0, fmaxf(s[nt][0], s[nt][1]));
            mx1 = fmaxf(mx1, fmaxf(s[nt][2], s[nt][3]));
        }
        mx0 = fmaxf(mx0, __shfl_xor_sync(0xffffffffu, mx0, 1, 4));
        mx0 = fmaxf(mx0, __shfl_xor_sync(0xffffffffu, mx0, 2, 4));
        mx1 = fmaxf(mx1, __shfl_xor_sync(0xffffffffu, mx1, 1, 4));
        mx1 = fmaxf(mx1, __shfl_xor_sync(0xffffffffu, mx1, 2, 4));

        const float mn0 = fmaxf(m0, mx0), mn1 = fmaxf(m1, mx1);
        const float mnC0 = mn0 * C, mnC1 = mn1 * C;
        const float al0 = exp2m(fmaf(m0, C, -mnC0));
        const float al1 = exp2m(fmaf(m1, C, -mnC1));
        m0 = mn0; m1 = mn1;

        // ---- exp2 (MUFU), one FMA per value ----
        float rs0 = 0.0f, rs1 = 0.0f;
        #pragma unroll
        for (int nt = 0; nt < 8; nt++) {
            s[nt][0] = exp2m(fmaf(s[nt][0], C, -mnC0));
            s[nt][1] = exp2m(fmaf(s[nt][1], C, -mnC0));
            s[nt][2] = exp2m(fmaf(s[nt][2], C, -mnC1));
            s[nt][3] = exp2m(fmaf(s[nt][3], C, -mnC1));
            rs0 += s[nt][0] + s[nt][1];
            rs1 += s[nt][2] + s[nt][3];
        }
        rs0 += __shfl_xor_sync(0xffffffffu, rs0, 1, 4);
        rs0 += __shfl_xor_sync(0xffffffffu, rs0, 2, 4);
        rs1 += __shfl_xor_sync(0xffffffffu, rs1, 1, 4);
        rs1 += __shfl_xor_sync(0xffffffffu, rs1, 2, 4);
        l0 = l0 * al0 + rs0;
        l1 = l1 * al1 + rs1;

        #pragma unroll
        for (int j = 0; j < 8; j++) {
            o[j][0] *= al0; o[j][1] *= al0;
            o[j][2] *= al1; o[j][3] *= al1;
        }

        // ---- O += P @ V (P C-frag as A-frag via sigma permutation) ----
        #pragma unroll
        for (int kc = 0; kc < 8; kc++) {
            uint4 a;
            a.x = f2tf32(s[kc][0]);
            a.y = f2tf32(s[kc][2]);
            a.z = f2tf32(s[kc][1]);
            a.w = f2tf32(s[kc][3]);
            const float* vr = &Vs[(kc * 8 + 2 * q) * AP];
            #pragma unroll
            for (int nd = 0; nd < 8; nd++) {
                uint2 bb;
                bb.x = __float_as_uint(vr[nd * 8 + g]);
                bb.y = __float_as_uint(vr[AP + nd * 8 + g]);
                mma_tf32(o[nd], a, bb);
            }
        }
        __syncthreads();   // all reads of buf kt&1 done before reuse at kt+2
    }

    // ---- epilogue: normalize, tf32-round (feeds proj GEMM), store ----
    float* ob = out + ((size_t)(b * S) + qt * 128) * 1024 + h * 64;
    const float inv0 = 1.0f / l0, inv1 = 1.0f / l1;
    #pragma unroll
    for (int nd = 0; nd < 8; nd++) {
        const int c = nd * 8 + 2 * q;
        float2 v0, v1;
        v0.x = tf32f(o[nd][0] * inv0); v0.y = tf32f(o[nd][1] * inv0);
        v1.x = tf32f(o[nd][2] * inv1); v1.y = tf32f(o[nd][3] * inv1);
        *(float2*)&ob[(size_t)pr * 1024 + c]       = v0;
        *(float2*)&ob[(size_t)(pr + 8) * 1024 + c] = v1;
    }
}

// ---------------- launch -------------------------------------------------
extern "C" void kernel_launch(void* const* d_in, const int* in_sizes, int n_in,
                              void* d_out, int out_size)
{
    const float* x      = (const float*)d_in[0];   // [4,2048,1024]
    const float* W_qkv  = (const float*)d_in[1];   // [1024,3072]
    const float* W_proj = (const float*)d_in[2];   // [1024,1024]
    const float* b_proj = (const float*)d_in[3];   // [1024]
    float* out = (float*)d_out;

    float *qkv = nullptr, *att = nullptr, *xr = nullptr, *wqT = nullptr, *wpT = nullptr;
    cudaGetSymbolAddress((void**)&qkv, g_qkv);
    cudaGetSymbolAddress((void**)&att, g_att);
    cudaGetSymbolAddress((void**)&xr,  g_xr);
    cudaGetSymbolAddress((void**)&wqT, g_wqT);
    cudaGetSymbolAddress((void**)&wpT, g_wpT);

    cudaFuncSetAttribute(attn_tc,
                         cudaFuncAttributeMaxDynamicSharedMemorySize, ATTN_SMEM);
    cudaFuncSetAttribute(gemm_cp,
                         cudaFuncAttributeMaxDynamicSharedMemorySize, GEMM_SMEM);

    const int M = 8192;

    // 0) pre-round x; transpose+round weights
    round_rna_vec<<<(M * 1024 / 4 + 255) / 256, 256>>>(
        (const float4*)x, (float4*)xr, M * 1024 / 4);
    transpose_rna<<<dim3(3072 / 32, 1024 / 32), 256>>>(W_qkv, wqT, 1024, 3072);
    transpose_rna<<<dim3(1024 / 32, 1024 / 32), 256>>>(W_proj, wpT, 1024, 1024);

    // 1) qkv = x @ W_qkv  (rounded output for raw attn staging)
    gemm_cp<<<dim3(3072 / 128, M / 128), 256, GEMM_SMEM>>>(
        xr, wqT, nullptr, qkv, M, 3072, 1024, 1);

    // 2) causal flash attention (tf32 mma.sync, cp.async pipelined)
    attn_tc<<<dim3(16, 16, 4), 256, ATTN_SMEM>>>(qkv, att);

    // 3) out = att @ W_proj + b_proj  (final output, unrounded)
    gemm_cp<<<dim3(1024 / 128, M / 128), 256, GEMM_SMEM>>>(
        att, wpT, b_proj, out, M, 1024, 1024, 0);
}